// round 13
// baseline (speedup 1.0000x reference)
#include <cuda_runtime.h>
#include <cstdint>
#include <math.h>

#define NTOK 2048
#define HD   2048
#define ID   7168
#define NE   8
#define NR   64
#define EC   (NE*NR)       // 512
#define KDOWN (ID+EC)      // 7680
#define NF   (2*ID+2*EC)   // 15360
#define SCALE 0.25f
#define NSLOT (2*NTOK)     // 4096
#define MAXTILE 40

// main GEMM tiling: 128x128x32, 3 stages, 128 threads (4 warps, 2x2 of 64x64)
#define BM 128
#define BN 128
#define STAGES 3
#define STAGE_FLOATS 8192
#define STAGE_BYTES  32768
#define SMEM_BYTES   (STAGES*STAGE_BYTES)

// gateup v3: B resident (16384 floats) + 2 A buffers (16384 floats each) = 192KB
#define GU_SMEM_BYTES 196608

// corr kernel: 128x64x32, 3 stages
#define CK 1792
#define C_STAGE_FLOATS 6144
#define C_STAGE_BYTES 24576
#define C_SMEM_BYTES (3*C_STAGE_BYTES)

// ---------------- scratch ----------------
__device__ float g_xc     [(size_t)NTOK*HD];
__device__ float g_fusedW [(size_t)NF*HD];
__device__ float g_baseout[(size_t)NTOK*NF];
__device__ float g_hs     [(size_t)NSLOT*ID];
__device__ float g_hmixext[(size_t)NTOK*KDOWN];
__device__ float g_corrp  [(size_t)4*NSLOT*NR];
__device__ float g_bcomb  [(size_t)HD*KDOWN];
__device__ float g_dac    [(size_t)EC*ID];
__device__ float g_gBc    [(size_t)NE*ID*NR];
__device__ float g_uBc    [(size_t)NE*ID*NR];
__device__ int   g_eids   [NSLOT];
__device__ float g_wts    [NSLOT];
__device__ int   g_cnt    [NE];
__device__ int   g_list   [NE*NSLOT];
__device__ int   g_tile_e [MAXTILE+8];
__device__ int   g_tile_base[MAXTILE+8];
__device__ int   g_ntiles;

// ---------------- helpers ----------------
__device__ __forceinline__ float f2tf32f(float x){
    uint32_t r;
    asm("cvt.rna.tf32.f32 %0, %1;" : "=r"(r) : "f"(x));
    return __uint_as_float(r);
}
__device__ __forceinline__ void mma_tf32(float* c, const uint32_t* a, const uint32_t* b){
    asm volatile(
        "mma.sync.aligned.m16n8k8.row.col.f32.tf32.tf32.f32 "
        "{%0,%1,%2,%3}, {%4,%5,%6,%7}, {%8,%9}, {%0,%1,%2,%3};"
        : "+f"(c[0]), "+f"(c[1]), "+f"(c[2]), "+f"(c[3])
        : "r"(a[0]), "r"(a[1]), "r"(a[2]), "r"(a[3]), "r"(b[0]), "r"(b[1]));
}
__device__ __forceinline__ void cp16(uint32_t smaddr, const void* g){
    asm volatile("cp.async.cg.shared.global [%0], [%1], 16;" :: "r"(smaddr), "l"(g));
}
__device__ __forceinline__ void cp16z(uint32_t smaddr, const void* g, uint32_t bytes){
    asm volatile("cp.async.cg.shared.global [%0], [%1], 16, %2;"
                 :: "r"(smaddr), "l"(g), "r"(bytes));
}
__device__ __forceinline__ void cp_commit(){
    asm volatile("cp.async.commit_group;" ::: "memory");
}
template<int N> __device__ __forceinline__ void cp_wait(){
    asm volatile("cp.async.wait_group %0;" :: "n"(N) : "memory");
}

// ---------------- main tf32 GEMM: C[M,N] (+)= A[M,K]*B[N,K]^T ----------------
__global__ __launch_bounds__(128, 2) void gemm_tf32(
        const float* __restrict__ A, const float* __restrict__ B,
        float* __restrict__ C, int M, int N, int K, int lda, int ldb,
        int roundN, int accum){
    extern __shared__ float sm[];
    const int tid = threadIdx.x;
    const int wid = tid >> 5, lane = tid & 31;
    const int wm = wid >> 1, wn = wid & 1;
    const int grp = lane >> 2, tig = lane & 3;
    const int m0 = blockIdx.y * BM, n0 = blockIdx.x * BN;
    uint32_t smem_base = (uint32_t)__cvta_generic_to_shared(sm);

    const int rA = tid >> 3;
    const int cc = (tid & 7) << 2;
    const uint32_t ccs = (uint32_t)cc ^ (((uint32_t)(rA & 7)) << 2);
    const float* Agp = A + (size_t)(m0 + rA) * lda + cc;
    const float* Bgp = B + (size_t)(n0 + rA) * ldb + cc;
    const size_t rstepA = (size_t)16 * lda;
    const size_t rstepB = (size_t)16 * ldb;

    uint32_t dstA[8], dstB[8];
    #pragma unroll
    for (int q = 0; q < 8; q++){
        dstA[q] = ((uint32_t)(rA + 16*q) * 32u + ccs) * 4u;
        dstB[q] = 16384u + dstA[q];
    }
    const int nch = K >> 5;

    #pragma unroll
    for (int s = 0; s < STAGES-1; s++){
        if (s < nch){
            uint32_t base = smem_base + (uint32_t)s * STAGE_BYTES;
            const float* ag = Agp + (s << 5);
            const float* bg = Bgp + (s << 5);
            #pragma unroll
            for (int q = 0; q < 8; q++) cp16(base + dstA[q], ag + rstepA * q);
            #pragma unroll
            for (int q = 0; q < 8; q++) cp16(base + dstB[q], bg + rstepB * q);
        }
        cp_commit();
    }

    const uint32_t gx = (uint32_t)grp << 2;
    uint32_t aRow[4], bRow[8];
    #pragma unroll
    for (int i = 0; i < 4; i++) aRow[i] = (uint32_t)(wm*64 + i*16 + grp) * 32u;
    #pragma unroll
    for (int j = 0; j < 8; j++) bRow[j] = 4096u + (uint32_t)(wn*64 + j*8 + grp) * 32u;

    float acc[4][8][4];
    #pragma unroll
    for (int i = 0; i < 4; i++)
        #pragma unroll
        for (int j = 0; j < 8; j++)
            #pragma unroll
            for (int q = 0; q < 4; q++) acc[i][j][q] = 0.f;

    for (int c = 0; c < nch; c++){
        cp_wait<STAGES-2>();
        __syncthreads();
        if (c + STAGES-1 < nch){
            const int cn = c + STAGES-1;
            uint32_t base = smem_base + (uint32_t)(cn % STAGES) * STAGE_BYTES;
            const float* ag = Agp + (cn << 5);
            const float* bg = Bgp + (cn << 5);
            #pragma unroll
            for (int q = 0; q < 8; q++) cp16(base + dstA[q], ag + rstepA * q);
            #pragma unroll
            for (int q = 0; q < 8; q++) cp16(base + dstB[q], bg + rstepB * q);
        }
        cp_commit();

        const uint32_t* st = (const uint32_t*)(sm + (size_t)(c % STAGES) * STAGE_FLOATS);
        #pragma unroll
        for (int kk = 0; kk < 4; kk++){
            const uint32_t k0 = ((uint32_t)(kk*8) + tig) ^ gx;
            const uint32_t k1 = ((uint32_t)(kk*8) + tig + 4u) ^ gx;
            uint32_t af[4][4], bf[8][2];
            #pragma unroll
            for (int i = 0; i < 4; i++){
                af[i][0] = st[aRow[i] + k0];
                af[i][1] = st[aRow[i] + 256u + k0];
                af[i][2] = st[aRow[i] + k1];
                af[i][3] = st[aRow[i] + 256u + k1];
            }
            #pragma unroll
            for (int j = 0; j < 8; j++){
                bf[j][0] = st[bRow[j] + k0];
                bf[j][1] = st[bRow[j] + k1];
            }
            #pragma unroll
            for (int i = 0; i < 4; i++)
                #pragma unroll
                for (int j = 0; j < 8; j++)
                    mma_tf32(acc[i][j], af[i], bf[j]);
        }
    }

    #pragma unroll
    for (int i = 0; i < 4; i++){
        int r0 = m0 + wm*64 + i*16 + grp;
        float* cr0 = C + (size_t)r0 * N;
        float* cr1 = C + (size_t)(r0 + 8) * N;
        #pragma unroll
        for (int j = 0; j < 8; j++){
            int col = n0 + wn*64 + j*8 + (tig << 1);
            float v0 = acc[i][j][0], v1 = acc[i][j][1];
            float v2 = acc[i][j][2], v3 = acc[i][j][3];
            if (accum){
                float2 o0 = *(const float2*)(cr0 + col);
                float2 o1 = *(const float2*)(cr1 + col);
                v0 += o0.x; v1 += o0.y; v2 += o1.x; v3 += o1.y;
            }
            if (col >= roundN){
                v0 = f2tf32f(v0); v1 = f2tf32f(v1);
                v2 = f2tf32f(v2); v3 = f2tf32f(v3);
            }
            *(float2*)(cr0 + col) = make_float2(v0, v1);
            *(float2*)(cr1 + col) = make_float2(v2, v3);
        }
    }
}

// ---------------- conv ----------------
__global__ void conv_kernel(const float* __restrict__ in, float* __restrict__ out){
    size_t i4 = ((size_t)blockIdx.x * 256 + threadIdx.x) << 2;
    float4 v = *(const float4*)(in + i4);
    v.x = f2tf32f(v.x); v.y = f2tf32f(v.y); v.z = f2tf32f(v.z); v.w = f2tf32f(v.w);
    *(float4*)(out + i4) = v;
}

// ---------------- routing + scatter ----------------
__global__ void zero_cnt_kernel(){ if (threadIdx.x < NE) g_cnt[threadIdx.x] = 0; }

__global__ void routing_kernel(const float* __restrict__ x,
                               const float* __restrict__ cw,
                               const float* __restrict__ cb,
                               const float* __restrict__ wealth){
    int t = blockIdx.x;
    int w = threadIdx.x >> 5, lane = threadIdx.x & 31;
    const float* xr = x + (size_t)t * HD;
    const float* cr = cw + (size_t)w * HD;
    float s = 0.f;
    for (int j = lane; j < HD; j += 32) s += xr[j] * cr[j];
    #pragma unroll
    for (int o = 16; o; o >>= 1) s += __shfl_down_sync(0xffffffffu, s, o);
    __shared__ float bids[NE];
    if (lane == 0){
        float conf = 1.f / (1.f + expf(-(s + cb[w])));
        bids[w] = conf * wealth[w];
    }
    __syncthreads();
    if (threadIdx.x == 0){
        int e0 = 0; float b0 = bids[0];
        for (int e = 1; e < NE; e++) if (bids[e] > b0){ b0 = bids[e]; e0 = e; }
        int e1 = -1; float b1 = -1e30f;
        for (int e = 0; e < NE; e++) if (e != e0 && bids[e] > b1){ b1 = bids[e]; e1 = e; }
        float ed = expf(b1 - b0);
        float inv = 1.f / (1.f + ed);
        g_eids[2*t] = e0; g_eids[2*t+1] = e1;
        g_wts [2*t] = inv; g_wts [2*t+1] = ed * inv;
        int p0 = atomicAdd(&g_cnt[e0], 1); g_list[e0*NSLOT + p0] = 2*t;
        int p1 = atomicAdd(&g_cnt[e1], 1); g_list[e1*NSLOT + p1] = 2*t + 1;
    }
}

__global__ void tilemeta_kernel(){
    if (threadIdx.x == 0){
        int nt = 0;
        for (int e = 0; e < NE; e++){
            int c = g_cnt[e];
            for (int b = 0; b < c; b += 128){
                g_tile_e[nt] = e; g_tile_base[nt] = b; nt++;
            }
        }
        g_ntiles = nt;
    }
}

// ---------------- gateup v3: persistent per-(i-tile, expert) CTA ----------------
// SMEM floats: Bg[0..8191] Bu[8192..16383] | Abuf0 Ag/Au [16384..32767] | Abuf1 [32768..49151]
__global__ __launch_bounds__(256, 1) void gateup_kernel(){
    const int e = blockIdx.y;
    const int cnt = g_cnt[e];
    if (cnt == 0) return;
    const int nb = (cnt + 127) >> 7;
    const int i0 = blockIdx.x << 7;
    extern __shared__ float sm[];
    __shared__ int s_ent[2][128];
    const int tid = threadIdx.x;
    uint32_t smem_base = (uint32_t)__cvta_generic_to_shared(sm);

    const int rA = tid >> 3;
    const int cc = (tid & 7) << 2;
    const uint32_t ccs = (uint32_t)cc ^ (((uint32_t)(rA & 7)) << 2);

    // B once: Bg at byte 0, Bu at byte 32768
    #pragma unroll
    for (int q = 0; q < 4; q++){
        const int row = rA + 32*q;
        const float* bsrcg = g_gBc + ((size_t)e*ID + i0 + row)*NR;
        const float* bsrcu = g_uBc + ((size_t)e*ID + i0 + row)*NR;
        #pragma unroll
        for (int ch = 0; ch < 2; ch++){
            const uint32_t dst = ((uint32_t)ch*4096u + (uint32_t)row*32u + ccs)*4u;
            const int kof = ch*32 + cc;
            cp16(smem_base + dst,           bsrcg + kof);
            cp16(smem_base + 32768u + dst,  bsrcu + kof);
        }
    }
    // ents tile 0
    if (tid < 128) s_ent[0][tid] = (tid < cnt) ? g_list[e*NSLOT + tid] : -1;
    __syncthreads();
    // A tile 0 into buf 0
    {
        const uint32_t abase = smem_base + 65536u;
        #pragma unroll
        for (int q = 0; q < 4; q++){
            const int row = rA + 32*q;
            const int ent = s_ent[0][row];
            const int t = ent >> 1;
            const uint32_t abytes = (ent >= 0) ? 16u : 0u;
            const float* asrc = (ent >= 0)
                ? (g_baseout + (size_t)t*NF + 2*ID + e*NR) : g_baseout;
            #pragma unroll
            for (int ch = 0; ch < 2; ch++){
                const uint32_t dst = ((uint32_t)ch*4096u + (uint32_t)row*32u + ccs)*4u;
                const int kof = ch*32 + cc;
                cp16z(abase + dst,           asrc + kof,      abytes);
                cp16z(abase + 32768u + dst,  asrc + EC + kof, abytes);
            }
        }
        cp_commit();
    }

    const int wid = tid >> 5, lane = tid & 31;
    const int wm = wid >> 2, wn = wid & 3;
    const int grp = lane >> 2, tig = lane & 3;
    const uint32_t gx = (uint32_t)grp << 2;
    uint32_t aRowO[4], bRowO[4];
    #pragma unroll
    for (int i = 0; i < 4; i++) aRowO[i] = (uint32_t)(wm*64 + i*16 + grp) * 32u;
    #pragma unroll
    for (int j = 0; j < 4; j++) bRowO[j] = (uint32_t)(wn*32 + j*8 + grp) * 32u;
    const uint32_t* uBg = (const uint32_t*)sm;
    const uint32_t* uBu = (const uint32_t*)(sm + 8192);

    for (int tb = 0; tb < nb; tb++){
        const int cur = tb & 1;
        cp_wait<0>();
        __syncthreads();
        // prefetch ents for next tile
        if (tb + 1 < nb && tid < 128){
            int j = (tb+1)*128 + tid;
            s_ent[cur^1][tid] = (j < cnt) ? g_list[e*NSLOT + j] : -1;
        }
        __syncthreads();
        if (tb + 1 < nb){
            const uint32_t abase = smem_base + 65536u + (uint32_t)(cur^1)*65536u;
            #pragma unroll
            for (int q = 0; q < 4; q++){
                const int row = rA + 32*q;
                const int ent = s_ent[cur^1][row];
                const int t = ent >> 1;
                const uint32_t abytes = (ent >= 0) ? 16u : 0u;
                const float* asrc = (ent >= 0)
                    ? (g_baseout + (size_t)t*NF + 2*ID + e*NR) : g_baseout;
                #pragma unroll
                for (int ch = 0; ch < 2; ch++){
                    const uint32_t dst = ((uint32_t)ch*4096u + (uint32_t)row*32u + ccs)*4u;
                    const int kof = ch*32 + cc;
                    cp16z(abase + dst,           asrc + kof,      abytes);
                    cp16z(abase + 32768u + dst,  asrc + EC + kof, abytes);
                }
            }
        }
        cp_commit();

        const uint32_t* uAg = (const uint32_t*)(sm + 16384 + cur*16384);
        const uint32_t* uAu = uAg + 8192;

        float accg[4][4][4], accu[4][4][4];
        #pragma unroll
        for (int i = 0; i < 4; i++)
            #pragma unroll
            for (int j = 0; j < 4; j++)
                #pragma unroll
                for (int q = 0; q < 4; q++){ accg[i][j][q]=0.f; accu[i][j][q]=0.f; }

        #pragma unroll
        for (int ch = 0; ch < 2; ch++){
            const uint32_t cb = (uint32_t)ch * 4096u;
            #pragma unroll
            for (int kk = 0; kk < 4; kk++){
                const uint32_t k0 = ((uint32_t)(kk*8) + tig) ^ gx;
                const uint32_t k1 = ((uint32_t)(kk*8) + tig + 4u) ^ gx;
                uint32_t ag[4][4], au[4][4], bg[4][2], bu[4][2];
                #pragma unroll
                for (int i = 0; i < 4; i++){
                    ag[i][0] = uAg[cb + aRowO[i] + k0];
                    ag[i][1] = uAg[cb + aRowO[i] + 256u + k0];
                    ag[i][2] = uAg[cb + aRowO[i] + k1];
                    ag[i][3] = uAg[cb + aRowO[i] + 256u + k1];
                    au[i][0] = uAu[cb + aRowO[i] + k0];
                    au[i][1] = uAu[cb + aRowO[i] + 256u + k0];
                    au[i][2] = uAu[cb + aRowO[i] + k1];
                    au[i][3] = uAu[cb + aRowO[i] + 256u + k1];
                }
                #pragma unroll
                for (int j = 0; j < 4; j++){
                    bg[j][0] = uBg[cb + bRowO[j] + k0];
                    bg[j][1] = uBg[cb + bRowO[j] + k1];
                    bu[j][0] = uBu[cb + bRowO[j] + k0];
                    bu[j][1] = uBu[cb + bRowO[j] + k1];
                }
                #pragma unroll
                for (int i = 0; i < 4; i++)
                    #pragma unroll
                    for (int j = 0; j < 4; j++){
                        mma_tf32(accg[i][j], ag[i], bg[j]);
                        mma_tf32(accu[i][j], au[i], bu[j]);
                    }
            }
        }

        // epilogue
        #pragma unroll
        for (int i = 0; i < 4; i++){
            #pragma unroll
            for (int half = 0; half < 2; half++){
                int r = wm*64 + i*16 + grp + half*8;
                int ent = s_ent[cur][r];
                if (ent < 0) continue;
                int t = ent >> 1;
                float w = g_wts[ent];
                const float* brow = g_baseout + (size_t)t*NF;
                float* hrow = g_hs + (size_t)ent*ID;
                #pragma unroll
                for (int j = 0; j < 4; j++){
                    int col = i0 + wn*32 + j*8 + (tig << 1);
                    float2 bg2 = *(const float2*)(brow + col);
                    float2 bu2 = *(const float2*)(brow + ID + col);
                    float cg0 = accg[i][j][half*2+0], cg1 = accg[i][j][half*2+1];
                    float cu0 = accu[i][j][half*2+0], cu1 = accu[i][j][half*2+1];
                    float gate0 = bg2.x + SCALE*cg0, gate1 = bg2.y + SCALE*cg1;
                    float up0 = bu2.x + SCALE*cu0,  up1 = bu2.y + SCALE*cu1;
                    float h0 = gate0 * (1.f/(1.f+__expf(-gate0))) * up0;
                    float h1 = gate1 * (1.f/(1.f+__expf(-gate1))) * up1;
                    *(float2*)(hrow + col) = make_float2(f2tf32f(w*h0), f2tf32f(w*h1));
                }
            }
        }
    }
}

// ---------------- grouped corr GEMM ----------------
__global__ __launch_bounds__(128, 2) void corr_kernel(){
    int tileid = blockIdx.y;
    if (tileid >= g_ntiles) return;
    const int e = g_tile_e[tileid];
    const int tbase = g_tile_base[tileid];
    const int cnt = g_cnt[e];
    const int ks = blockIdx.x;
    extern __shared__ float sm[];
    __shared__ int s_ent[128];
    const int tid = threadIdx.x;
    if (tid < 128){
        int j = tbase + tid;
        s_ent[tid] = (j < cnt) ? g_list[e*NSLOT + j] : -1;
    }
    __syncthreads();
    uint32_t smem_base = (uint32_t)__cvta_generic_to_shared(sm);

    const int rA = tid >> 3;
    const int cc = (tid & 7) << 2;
    const uint32_t ccs = (uint32_t)cc ^ (((uint32_t)(rA & 7)) << 2);
    const size_t koff0 = (size_t)ks*CK + cc;

    const float* Asrc[8]; uint32_t Abytes[8];
    #pragma unroll
    for (int q = 0; q < 8; q++){
        int ent = s_ent[rA + 16*q];
        Asrc[q] = (ent >= 0) ? (g_hs + (size_t)ent*ID + koff0) : g_hs;
        Abytes[q] = (ent >= 0) ? 16u : 0u;
    }
    const float* Bsrc[4];
    #pragma unroll
    for (int q = 0; q < 4; q++)
        Bsrc[q] = g_dac + (size_t)(e*NR + rA + 16*q)*ID + koff0;

    uint32_t dstA[8], dstB[4];
    #pragma unroll
    for (int q = 0; q < 8; q++) dstA[q] = ((uint32_t)(rA + 16*q) * 32u + ccs) * 4u;
    #pragma unroll
    for (int q = 0; q < 4; q++) dstB[q] = 16384u + ((uint32_t)(rA + 16*q) * 32u + ccs) * 4u;

    const int nch = CK >> 5;

    #pragma unroll
    for (int s = 0; s < 2; s++){
        uint32_t base = smem_base + (uint32_t)s * C_STAGE_BYTES;
        #pragma unroll
        for (int q = 0; q < 8; q++) cp16z(base + dstA[q], Asrc[q] + (s<<5), Abytes[q]);
        #pragma unroll
        for (int q = 0; q < 4; q++) cp16(base + dstB[q], Bsrc[q] + (s<<5));
        cp_commit();
    }

    const int wid = tid >> 5, lane = tid & 31;
    const int wm = wid >> 1, wn = wid & 1;
    const int grp = lane >> 2, tig = lane & 3;
    const uint32_t gx = (uint32_t)grp << 2;
    uint32_t aRow[4], bRow[4];
    #pragma unroll
    for (int i = 0; i < 4; i++) aRow[i] = (uint32_t)(wm*64 + i*16 + grp) * 32u;
    #pragma unroll
    for (int j = 0; j < 4; j++) bRow[j] = 4096u + (uint32_t)(wn*32 + j*8 + grp) * 32u;

    float acc[4][4][4];
    #pragma unroll
    for (int i = 0; i < 4; i++)
        #pragma unroll
        for (int j = 0; j < 4; j++)
            #pragma unroll
            for (int q = 0; q < 4; q++) acc[i][j][q] = 0.f;

    for (int c = 0; c < nch; c++){
        cp_wait<1>();
        __syncthreads();
        if (c + 2 < nch){
            const int cn = c + 2;
            uint32_t base = smem_base + (uint32_t)(cn % 3) * C_STAGE_BYTES;
            #pragma unroll
            for (int q = 0; q < 8; q++) cp16z(base + dstA[q], Asrc[q] + (cn<<5), Abytes[q]);
            #pragma unroll
            for (int q = 0; q < 4; q++) cp16(base + dstB[q], Bsrc[q] + (cn<<5));
        }
        cp_commit();

        const uint32_t* st = (const uint32_t*)(sm + (size_t)(c % 3) * C_STAGE_FLOATS);
        #pragma unroll
        for (int kk = 0; kk < 4; kk++){
            const uint32_t k0 = ((uint32_t)(kk*8) + tig) ^ gx;
            const uint32_t k1 = ((uint32_t)(kk*8) + tig + 4u) ^ gx;
            uint32_t af[4][4], bf[4][2];
            #pragma unroll
            for (int i = 0; i < 4; i++){
                af[i][0] = st[aRow[i] + k0];
                af[i][1] = st[aRow[i] + 256u + k0];
                af[i][2] = st[aRow[i] + k1];
                af[i][3] = st[aRow[i] + 256u + k1];
            }
            #pragma unroll
            for (int j = 0; j < 4; j++){
                bf[j][0] = st[bRow[j] + k0];
                bf[j][1] = st[bRow[j] + k1];
            }
            #pragma unroll
            for (int i = 0; i < 4; i++)
                #pragma unroll
                for (int j = 0; j < 4; j++)
                    mma_tf32(acc[i][j], af[i], bf[j]);
        }
    }

    #pragma unroll
    for (int i = 0; i < 4; i++){
        #pragma unroll
        for (int half = 0; half < 2; half++){
            int r = wm*64 + i*16 + grp + half*8;
            int ent = s_ent[r];
            if (ent < 0) continue;
            float* crow = g_corrp + ((size_t)ks*NSLOT + ent)*NR;
            #pragma unroll
            for (int j = 0; j < 4; j++){
                int col = wn*32 + j*8 + (tig << 1);
                *(float2*)(crow + col) =
                    make_float2(acc[i][j][half*2+0], acc[i][j][half*2+1]);
            }
        }
    }
}

// ---------------- bcomb ----------------
__global__ void bcomb_kernel(const float* __restrict__ bdw, const float* __restrict__ dB){
    size_t idx = (size_t)blockIdx.x * 256 + threadIdx.x;
    int h = (int)(idx / KDOWN); int k = (int)(idx % KDOWN);
    float v;
    if (k < ID) v = bdw[(size_t)h * ID + k];
    else { int j = k - ID; int e = j >> 6; int r = j & 63;
           v = dB[((size_t)e * HD + h) * NR + r]; }
    g_bcomb[idx] = f2tf32f(v);
}

// hmix head: hs0+hs1
__global__ void addhead_kernel(){
    size_t i4 = ((size_t)blockIdx.x * 256 + threadIdx.x) << 2;
    int t = (int)(i4 / ID); int col = (int)(i4 % ID);
    float4 a = *(const float4*)&g_hs[(size_t)(2*t)*ID + col];
    float4 b = *(const float4*)&g_hs[(size_t)(2*t+1)*ID + col];
    float4 o;
    o.x = f2tf32f(a.x+b.x); o.y = f2tf32f(a.y+b.y);
    o.z = f2tf32f(a.z+b.z); o.w = f2tf32f(a.w+b.w);
    *(float4*)&g_hmixext[(size_t)t * KDOWN + col] = o;
}

// cvec tail
__global__ void cvec_kernel(){
    int idx = blockIdx.x * 256 + threadIdx.x;
    int t = idx >> 9, j = idx & 511;
    int e = j >> 6, r = j & 63;
    float v = 0.f;
    #pragma unroll
    for (int k = 0; k < 2; k++){
        int ent = 2*t + k;
        if (g_eids[ent] == e){
            #pragma unroll
            for (int s = 0; s < 4; s++)
                v += g_corrp[((size_t)s*NSLOT + ent)*NR + r];
        }
    }
    g_hmixext[(size_t)t * KDOWN + ID + j] = f2tf32f(SCALE * v);
}

// ---------------- launch ----------------
static void launch_gemm_s(cudaStream_t st, const float* A, const float* B, float* C,
                          int M, int N, int K, int lda, int ldb, int roundN, int accum){
    dim3 grid(N / BN, M / BM);
    gemm_tf32<<<grid, 128, SMEM_BYTES, st>>>(A, B, C, M, N, K, lda, ldb, roundN, accum);
}
static void launch_conv_s(cudaStream_t st, const float* in, float* out, size_t n){
    conv_kernel<<<(unsigned)((n / 4) / 256), 256, 0, st>>>(in, out);
}

extern "C" void kernel_launch(void* const* d_in, const int* in_sizes, int n_in,
                              void* d_out, int out_size){
    const float* x      = (const float*)d_in[0];
    const float* conf_w = (const float*)d_in[1];
    const float* conf_b = (const float*)d_in[2];
    const float* wealth = (const float*)d_in[3];
    const float* bgw    = (const float*)d_in[4];
    const float* buw    = (const float*)d_in[5];
    const float* bdw    = (const float*)d_in[6];
    const float* gA     = (const float*)d_in[7];
    const float* gB     = (const float*)d_in[8];
    const float* uA     = (const float*)d_in[9];
    const float* uB     = (const float*)d_in[10];
    const float* dA     = (const float*)d_in[11];
    const float* dB     = (const float*)d_in[12];
    float* out = (float*)d_out;

    static bool init_done = false;
    static cudaStream_t s1, s2;
    static cudaEvent_t evFork, evS1, evS2, evGate, evAdd, evMain;
    if (!init_done){
        cudaFuncSetAttribute(gemm_tf32, cudaFuncAttributeMaxDynamicSharedMemorySize, SMEM_BYTES);
        cudaFuncSetAttribute(gateup_kernel, cudaFuncAttributeMaxDynamicSharedMemorySize, GU_SMEM_BYTES);
        cudaFuncSetAttribute(corr_kernel, cudaFuncAttributeMaxDynamicSharedMemorySize, C_SMEM_BYTES);
        cudaStreamCreateWithFlags(&s1, cudaStreamNonBlocking);
        cudaStreamCreateWithFlags(&s2, cudaStreamNonBlocking);
        cudaEventCreateWithFlags(&evFork, cudaEventDisableTiming);
        cudaEventCreateWithFlags(&evS1,   cudaEventDisableTiming);
        cudaEventCreateWithFlags(&evS2,   cudaEventDisableTiming);
        cudaEventCreateWithFlags(&evGate, cudaEventDisableTiming);
        cudaEventCreateWithFlags(&evAdd,  cudaEventDisableTiming);
        cudaEventCreateWithFlags(&evMain, cudaEventDisableTiming);
        init_done = true;
    }

    float *p_xc, *p_fusedW, *p_baseout, *p_hmixext, *p_dac, *p_bcomb, *p_gBc, *p_uBc;
    cudaGetSymbolAddress((void**)&p_xc,      g_xc);
    cudaGetSymbolAddress((void**)&p_fusedW,  g_fusedW);
    cudaGetSymbolAddress((void**)&p_baseout, g_baseout);
    cudaGetSymbolAddress((void**)&p_hmixext, g_hmixext);
    cudaGetSymbolAddress((void**)&p_dac,     g_dac);
    cudaGetSymbolAddress((void**)&p_bcomb,   g_bcomb);
    cudaGetSymbolAddress((void**)&p_gBc,     g_gBc);
    cudaGetSymbolAddress((void**)&p_uBc,     g_uBc);

    cudaStream_t s0 = 0;

    cudaEventRecord(evFork, s0);
    cudaStreamWaitEvent(s1, evFork, 0);
    cudaStreamWaitEvent(s2, evFork, 0);

    // s0: routing path + x conversion
    zero_cnt_kernel<<<1, 32, 0, s0>>>();
    routing_kernel<<<NTOK, 256, 0, s0>>>(x, conf_w, conf_b, wealth);
    tilemeta_kernel<<<1, 32, 0, s0>>>();
    launch_conv_s(s0, x, p_xc, (size_t)NTOK*HD);

    // s1: fusedW conversions
    launch_conv_s(s1, bgw, p_fusedW,                        (size_t)ID*HD);
    launch_conv_s(s1, buw, p_fusedW + (size_t)ID*HD,        (size_t)ID*HD);
    launch_conv_s(s1, gA,  p_fusedW + (size_t)2*ID*HD,      (size_t)EC*HD);
    launch_conv_s(s1, uA,  p_fusedW + (size_t)(2*ID+EC)*HD, (size_t)EC*HD);
    cudaEventRecord(evS1, s1);

    // s2: mid/down operand prep
    launch_conv_s(s2, gB, p_gBc, (size_t)NE*ID*NR);
    launch_conv_s(s2, uB, p_uBc, (size_t)NE*ID*NR);
    launch_conv_s(s2, dA, p_dac, (size_t)EC*ID);
    bcomb_kernel<<<((size_t)HD*KDOWN)/256, 256, 0, s2>>>(bdw, dB);
    cudaEventRecord(evS2, s2);

    // x-side fused GEMM
    cudaStreamWaitEvent(s0, evS1, 0);
    launch_gemm_s(s0, p_xc, p_fusedW, p_baseout, NTOK, NF, HD, HD, HD, 2*ID, 0);

    // gateup v3 (persistent per expert x i-tile)
    cudaStreamWaitEvent(s0, evS2, 0);
    gateup_kernel<<<dim3(ID/128, NE), 256, GU_SMEM_BYTES, s0>>>();
    cudaEventRecord(evGate, s0);

    // s1: addhead -> main down GEMM (K=ID) while s0 does corr+cvec
    cudaStreamWaitEvent(s1, evGate, 0);
    addhead_kernel<<<(NTOK*ID/4)/256, 256, 0, s1>>>();
    cudaEventRecord(evAdd, s1);
    launch_gemm_s(s1, p_hmixext, p_bcomb, out, NTOK, HD, ID, KDOWN, KDOWN, 1<<30, 0);
    cudaEventRecord(evMain, s1);

    // s0: down-LoRA correction path (overlapped with main down GEMM)
    corr_kernel<<<dim3(4, MAXTILE), 128, C_SMEM_BYTES, s0>>>();
    cvec_kernel<<<(NTOK*EC)/256, 256, 0, s0>>>();

    // accumulating tail down GEMM: out += cvec @ dBall^T
    cudaStreamWaitEvent(s0, evMain, 0);
    launch_gemm_s(s0, p_hmixext + ID, p_bcomb + ID, out, NTOK, HD, EC, KDOWN, KDOWN, 1<<30, 1);
}